// round 1
// baseline (speedup 1.0000x reference)
#include <cuda_runtime.h>
#include <math.h>

#define BATCH 8
#define CH 64
#define HIN 224
#define WIN 224
#define PLANE (HIN*WIN)         /* 50176 */
#define HWTILES (PLANE/32)      /* 1568  */
#define NTILES (BATCH*HWTILES)  /* 12544 */
#define CMID 32
#define GH 64                   /* small grid rows  */
#define GW 128                  /* small grid cols  */
#define PH 64                   /* pooled H */
#define PW 128                  /* pooled W */
#define POOLED_ELEMS (BATCH*CH*PH*PW)  /* 4194304 */

// ---------------- device scratch (static, no allocations) ----------------
__device__ float  g_xT[(size_t)BATCH*PLANE*CH];   // x transposed to [B][H][W][C]
__device__ float  g_part[(size_t)NTILES*CH];      // per-tile channel partial sums
__device__ float  g_branch[BATCH*CH];             // global mean per (b,c)
__device__ float  g_lohi[BATCH*2];                // lo, hi per b
__device__ float  g_cval[BATCH*CH];               // constant-region bilinear value
__device__ float2 g_coords[BATCH*GH*GW];          // (ix,iy) per (b,i,j)

// ---------------- kernel 1: tiled transpose + channel partial sums -------
__global__ void k_transpose(const float* __restrict__ x) {
    __shared__ float tile[CH][33];
    int bx   = blockIdx.x;              // 0..NTILES-1
    int b    = bx / HWTILES;
    int tidx = bx % HWTILES;
    int t0   = tidx * 32;               // hw offset of this 32-wide tile
    int tid  = threadIdx.x;             // 256 threads

    const float4* xp = (const float4*)(x + (size_t)b * CH * PLANE);
    int base4 = t0 >> 2;
#pragma unroll
    for (int it = 0; it < 2; it++) {
        int p    = it * 256 + tid;      // 0..511 float4 slots
        int c    = p >> 3;              // channel row 0..63
        int col4 = p & 7;               // float4 col 0..7
        float4 v = xp[(size_t)c * (PLANE / 4) + base4 + col4];
        tile[c][col4 * 4 + 0] = v.x;
        tile[c][col4 * 4 + 1] = v.y;
        tile[c][col4 * 4 + 2] = v.z;
        tile[c][col4 * 4 + 3] = v.w;
    }
    __syncthreads();

    // partial channel sums for the global mean
    if (tid < CH) {
        float s = 0.f;
#pragma unroll
        for (int k = 0; k < 32; k++) s += tile[tid][k];
        g_part[(size_t)bx * CH + tid] = s;
    }

    // transposed store: xT[b][hw][c], vectorized over c
    float4* xt = (float4*)g_xT;
#pragma unroll
    for (int it = 0; it < 2; it++) {
        int p  = it * 256 + tid;        // 0..511 float4 slots
        int rr = p >> 4;                // hw row within tile 0..31
        int c4 = p & 15;                // channel quad 0..15
        float4 v;
        v.x = tile[4 * c4 + 0][rr];
        v.y = tile[4 * c4 + 1][rr];
        v.z = tile[4 * c4 + 2][rr];
        v.w = tile[4 * c4 + 3][rr];
        xt[((size_t)b * PLANE + t0 + rr) * 16 + c4] = v;
    }
}

// ---------------- kernel 2: reduce partial sums -> branch means ----------
__global__ void k_mean(void) {
    __shared__ float sm[256];
    int b   = blockIdx.x;               // 8 blocks
    int tid = threadIdx.x;              // 256
    int c    = tid & 63;
    int part = tid >> 6;                // 0..3, each covers 392 tiles
    float s = 0.f;
    for (int q = 0; q < 392; q++) {
        int t = part * 392 + q;
        s += g_part[((size_t)b * HWTILES + t) * CH + c];
    }
    sm[tid] = s;
    __syncthreads();
    if (tid < 64) {
        float tot = sm[tid] + sm[tid + 64] + sm[tid + 128] + sm[tid + 192];
        g_branch[b * CH + tid] = tot * (1.0f / (float)PLANE);
    }
}

// ---------------- kernel 3: MLP -> weight, lo/hi; const bilinear values --
__global__ void k_mlp(const float* __restrict__ l,
                      const float* __restrict__ w1, const float* __restrict__ b1,
                      const float* __restrict__ w2, const float* __restrict__ b2,
                      const float* __restrict__ x,
                      float* __restrict__ outw) {
    __shared__ float hid[BATCH][CMID];
    __shared__ float wgt[BATCH][2];
    int tid = threadIdx.x;              // 256

    // constant-region bilinear values (independent of the MLP)
#pragma unroll
    for (int rep = 0; rep < 2; rep++) {
        int idx = rep * 256 + tid;      // 0..511 = (b,c)
        int b = idx >> 6, c = idx & 63;
        float gx = l[2 * b + 0], gy = l[2 * b + 1];
        float ix = fminf(fmaxf(((gx + 1.f) * WIN - 1.f) * 0.5f, 0.f), (float)(WIN - 1));
        float iy = fminf(fmaxf(((gy + 1.f) * HIN - 1.f) * 0.5f, 0.f), (float)(HIN - 1));
        float x0f = floorf(ix), y0f = floorf(iy);
        float wx = ix - x0f, wy = iy - y0f;
        int x0 = (int)x0f, y0 = (int)y0f;
        int x1 = min(x0 + 1, WIN - 1), y1 = min(y0 + 1, HIN - 1);
        const float* p = x + (size_t)(b * CH + c) * PLANE;
        float v = p[y0 * WIN + x0] * (1.f - wx) * (1.f - wy)
                + p[y0 * WIN + x1] * wx * (1.f - wy)
                + p[y1 * WIN + x0] * (1.f - wx) * wy
                + p[y1 * WIN + x1] * wx * wy;
        g_cval[idx] = v;
    }

    // hidden = relu(branch @ w1 + b1)
    {
        int b = tid >> 5, m = tid & 31; // 8*32 = 256 threads exactly
        float s = b1[m];
#pragma unroll
        for (int c = 0; c < CH; c++) s += g_branch[b * CH + c] * w1[c * CMID + m];
        hid[b][m] = fmaxf(s, 0.f);
    }
    __syncthreads();

    // weight = sigmoid(hidden @ w2 + b2)
    if (tid < 16) {
        int b = tid >> 1, k = tid & 1;
        float s = b2[k];
#pragma unroll
        for (int m = 0; m < CMID; m++) s += hid[b][m] * w2[m * 2 + k];
        float wv = 1.f / (1.f + expf(-s));
        wgt[b][k] = wv;
        outw[tid] = wv;                 // weight output (tuple element 2)
    }
    __syncthreads();
    if (tid < 8) {
        g_lohi[2 * tid + 0] = logf(wgt[tid][0] * 0.01f);   // R_MIN
        g_lohi[2 * tid + 1] = logf(wgt[tid][1] * 0.60f);   // R_MAX
    }
}

// ---------------- kernel 4: per-(b,i,j) sample coordinates ---------------
__global__ void k_coords(const float* __restrict__ l) {
    int idx = blockIdx.x * 256 + threadIdx.x;   // 65536
    int b = idx >> 13;
    int i = (idx >> 7) & 63;
    int j = idx & 127;
    float xg = (i - 32) * (1.0f / 32.0f);
    float yg = (j - 64) * (1.0f / 64.0f);
    float rad  = sqrtf(xg * xg + yg * yg);
    float logr = logf(fmaxf(rad, 1e-12f));
    float lo = g_lohi[2 * b], hi = g_lohi[2 * b + 1];
    float r = 64.f * (logr - lo) / (hi - lo);
    float a = atan2f(yg, xg);
    if (!(a > 0.f)) a += 6.283185307179586f;
    float gx = a * 0.3183098861837907f - 1.f + l[2 * b + 0];  // a/pi - 1 + l0
    float gy = r * (1.f / 32.f) - 1.f + l[2 * b + 1];
    float ix = fminf(fmaxf(((gx + 1.f) * WIN - 1.f) * 0.5f, 0.f), (float)(WIN - 1));
    float iy = fminf(fmaxf(((gy + 1.f) * HIN - 1.f) * 0.5f, 0.f), (float)(HIN - 1));
    g_coords[idx] = make_float2(ix, iy);
}

// ---------------- kernel 5: fill whole pooled with constant value --------
__global__ void k_fill(float* __restrict__ out) {
    int idx = blockIdx.x * 256 + threadIdx.x;   // 1048576 float4
    int plane = idx >> 11;                      // 2048 float4 per (b,c)
    float v = g_cval[plane];
    ((float4*)out)[idx] = make_float4(v, v, v, v);
}

// ---------------- kernel 6: inner log-polar gather + 4x4 pool ------------
__global__ void __launch_bounds__(256) k_inner(float* __restrict__ out) {
    int gtid = blockIdx.x * 256 + threadIdx.x;
    int wg   = gtid >> 5;                       // warp id 0..4095 (one per position)
    int lane = threadIdx.x & 31;
    int b   = wg >> 9;
    int pos = wg & 511;
    int h = pos >> 5, w = pos & 31;
    int half = lane >> 4;                       // 0: x0 column, 1: x1 column
    int c4   = lane & 15;                       // channel quad

    const float4* xt = (const float4*)g_xT;
    size_t basep = (size_t)b * PLANE * 16;      // float4 units

    float a0 = 0.f, a1 = 0.f, a2 = 0.f, a3 = 0.f;
#pragma unroll 4
    for (int s = 0; s < 16; s++) {
        int i = 4 * h + (s >> 2);
        int j = 4 * w + (s & 3);
        float2 co = g_coords[(b << 13) | (i << 7) | j];
        float x0f = floorf(co.x), y0f = floorf(co.y);
        float wx = co.x - x0f, wy = co.y - y0f;
        int x0 = (int)x0f, y0 = (int)y0f;
        int x1 = min(x0 + 1, WIN - 1), y1 = min(y0 + 1, HIN - 1);
        int xs = half ? x1 : x0;
        float wxs = half ? wx : (1.f - wx);
        float w0 = wxs * (1.f - wy);
        float w1v = wxs * wy;
        float4 v0 = xt[basep + (size_t)(y0 * WIN + xs) * 16 + c4];
        float4 v1 = xt[basep + (size_t)(y1 * WIN + xs) * 16 + c4];
        a0 += v0.x * w0 + v1.x * w1v;
        a1 += v0.y * w0 + v1.y * w1v;
        a2 += v0.z * w0 + v1.z * w1v;
        a3 += v0.w * w0 + v1.w * w1v;
    }
    // combine x0-column (lanes 0..15) with x1-column (lanes 16..31)
    a0 += __shfl_down_sync(0xffffffffu, a0, 16);
    a1 += __shfl_down_sync(0xffffffffu, a1, 16);
    a2 += __shfl_down_sync(0xffffffffu, a2, 16);
    a3 += __shfl_down_sync(0xffffffffu, a3, 16);

    if (half == 0) {
        const float sc = 1.f / 16.f;            // 4x4 avg pool
        int cbase = 4 * c4;
        size_t ob = ((size_t)(b * CH + cbase) * PH + h) * PW + w;
        out[ob]                       = a0 * sc;
        out[ob + (size_t)PH * PW]     = a1 * sc;
        out[ob + (size_t)2 * PH * PW] = a2 * sc;
        out[ob + (size_t)3 * PH * PW] = a3 * sc;
    }
}

// ---------------------------------------------------------------------
extern "C" void kernel_launch(void* const* d_in, const int* in_sizes, int n_in,
                              void* d_out, int out_size) {
    const float* x  = (const float*)d_in[0];   // [8,64,224,224]
    const float* l  = (const float*)d_in[1];   // [8,2]
    const float* w1 = (const float*)d_in[2];   // [64,32]
    const float* b1 = (const float*)d_in[3];   // [32]
    const float* w2 = (const float*)d_in[4];   // [32,2]
    const float* b2 = (const float*)d_in[5];   // [2]
    float* out = (float*)d_out;                // pooled [8,64,64,128] ++ weight [8,2]
    float* outw = out + POOLED_ELEMS;

    k_transpose<<<NTILES, 256>>>(x);
    k_mean<<<BATCH, 256>>>();
    k_mlp<<<1, 256>>>(l, w1, b1, w2, b2, x, outw);
    k_coords<<<BATCH * GH * GW / 256, 256>>>(l);
    k_fill<<<POOLED_ELEMS / 4 / 256, 256>>>(out);
    k_inner<<<(BATCH * 16 * 32 * 32) / 256, 256>>>(out);
}

// round 2
// speedup vs baseline: 1.5421x; 1.5421x over previous
#include <cuda_runtime.h>
#include <cuda_fp16.h>
#include <math.h>

#define BATCH 8
#define CH 64
#define HIN 224
#define WIN 224
#define PLANE (HIN*WIN)         /* 50176 */
#define HWTILES (PLANE/32)      /* 1568  */
#define NTILES (BATCH*HWTILES)  /* 12544 */
#define CMID 32
#define PH 64
#define PW 128
#define POOLED_ELEMS (BATCH*CH*PH*PW)  /* 4194304 */
#define NB_INNER 512
#define NB_FILL 4096

// ---------------- device scratch ----------------
__device__ __half g_xTh[(size_t)BATCH*PLANE*CH];  // x transposed [B][H][W][C] fp16
__device__ float  g_part[(size_t)NTILES*CH];      // per-tile channel partial sums
__device__ float  g_part2[64*CH];                 // second-stage partials
__device__ float  g_lohi[BATCH*2];                // lo, hi per b
__device__ float  g_cval[BATCH*CH];               // constant-region bilinear value
__device__ float2 g_polar[64*128];                // (logr, a/pi - 1) per (i,j)

// ------------- kernel 1: transpose -> fp16 + channel partial sums -------
__global__ void __launch_bounds__(256) k_transpose(const float* __restrict__ x) {
    __shared__ float tile[CH][33];
    int bx   = blockIdx.x;
    int b    = bx / HWTILES;
    int tidx = bx % HWTILES;
    int t0   = tidx * 32;
    int tid  = threadIdx.x;

    const float4* xp = (const float4*)(x + (size_t)b * CH * PLANE);
    int base4 = t0 >> 2;
#pragma unroll
    for (int it = 0; it < 2; it++) {
        int p    = it * 256 + tid;
        int c    = p >> 3;
        int col4 = p & 7;
        float4 v = xp[(size_t)c * (PLANE / 4) + base4 + col4];
        tile[c][col4 * 4 + 0] = v.x;
        tile[c][col4 * 4 + 1] = v.y;
        tile[c][col4 * 4 + 2] = v.z;
        tile[c][col4 * 4 + 3] = v.w;
    }
    __syncthreads();

    if (tid < CH) {
        float s = 0.f;
#pragma unroll
        for (int k = 0; k < 32; k++) s += tile[tid][k];
        g_part[(size_t)bx * CH + tid] = s;
    }

    // pack 8 channels (fp16) per uint4; 32 rows x 8 quads = 256 slots
    int rr = tid >> 3;
    int q  = tid & 7;
    half2 h0 = __floats2half2_rn(tile[8*q+0][rr], tile[8*q+1][rr]);
    half2 h1 = __floats2half2_rn(tile[8*q+2][rr], tile[8*q+3][rr]);
    half2 h2 = __floats2half2_rn(tile[8*q+4][rr], tile[8*q+5][rr]);
    half2 h3 = __floats2half2_rn(tile[8*q+6][rr], tile[8*q+7][rr]);
    uint4 u;
    u.x = *(unsigned int*)&h0;
    u.y = *(unsigned int*)&h1;
    u.z = *(unsigned int*)&h2;
    u.w = *(unsigned int*)&h3;
    ((uint4*)g_xTh)[((size_t)b * PLANE + t0 + rr) * 8 + q] = u;
}

// ------------- kernel 2: reduce partials (stage 2) + polar table --------
__global__ void __launch_bounds__(256) k_mean_table(void) {
    int blk = blockIdx.x;           // 0..63 = (b, part)
    int b = blk >> 3, part = blk & 7;
    int tid = threadIdx.x;
    int c = tid & 63, sub = tid >> 6;   // sub 0..3, 49 tiles each
    float s = 0.f;
    int t0 = part * 196 + sub * 49;
    for (int qq = 0; qq < 49; qq++)
        s += g_part[((size_t)b * HWTILES + t0 + qq) * CH + c];
    __shared__ float sm[256];
    sm[tid] = s;
    __syncthreads();
    if (tid < 64)
        g_part2[blk * 64 + tid] = sm[tid] + sm[tid+64] + sm[tid+128] + sm[tid+192];

    // polar table: 8192 entries / 64 blocks = 128 per block
    if (tid < 128) {
        int e = blk * 128 + tid;
        int i = e >> 7, j = e & 127;
        float xg = (i - 32) * (1.0f / 32.0f);
        float yg = (j - 64) * (1.0f / 64.0f);
        float logr = logf(fmaxf(sqrtf(xg*xg + yg*yg), 1e-12f));
        float a = atan2f(yg, xg);
        if (!(a > 0.f)) a += 6.283185307179586f;
        g_polar[e] = make_float2(logr, a * 0.3183098861837907f - 1.f);
    }
}

// ------------- kernel 3: final mean + MLP + lo/hi + const values --------
__global__ void __launch_bounds__(256) k_mlp(const float* __restrict__ l,
                      const float* __restrict__ w1, const float* __restrict__ b1,
                      const float* __restrict__ w2, const float* __restrict__ b2,
                      const float* __restrict__ x,
                      float* __restrict__ outw) {
    __shared__ float br[BATCH][CH];
    __shared__ float hid[BATCH][CMID];
    __shared__ float wgt[BATCH][2];
    int tid = threadIdx.x;

#pragma unroll
    for (int rep = 0; rep < 2; rep++) {
        int idx = rep * 256 + tid;       // (b,c)
        int b = idx >> 6, c = idx & 63;
        float s = 0.f;
#pragma unroll
        for (int p = 0; p < 8; p++) s += g_part2[(b * 8 + p) * 64 + c];
        br[b][c] = s * (1.0f / (float)PLANE);

        // constant-region bilinear value (independent of MLP)
        float gx = l[2*b + 0], gy = l[2*b + 1];
        float ix = fminf(fmaxf(((gx + 1.f) * WIN - 1.f) * 0.5f, 0.f), (float)(WIN - 1));
        float iy = fminf(fmaxf(((gy + 1.f) * HIN - 1.f) * 0.5f, 0.f), (float)(HIN - 1));
        float x0f = floorf(ix), y0f = floorf(iy);
        float wx = ix - x0f, wy = iy - y0f;
        int x0 = (int)x0f, y0 = (int)y0f;
        int x1 = min(x0 + 1, WIN - 1), y1 = min(y0 + 1, HIN - 1);
        const float* p = x + (size_t)(b * CH + c) * PLANE;
        float v = p[y0 * WIN + x0] * (1.f - wx) * (1.f - wy)
                + p[y0 * WIN + x1] * wx * (1.f - wy)
                + p[y1 * WIN + x0] * (1.f - wx) * wy
                + p[y1 * WIN + x1] * wx * wy;
        g_cval[idx] = v;
    }
    __syncthreads();

    {
        int b = tid >> 5, m = tid & 31;
        float s = b1[m];
#pragma unroll
        for (int c = 0; c < CH; c++) s += br[b][c] * w1[c * CMID + m];
        hid[b][m] = fmaxf(s, 0.f);
    }
    __syncthreads();

    if (tid < 16) {
        int b = tid >> 1, k = tid & 1;
        float s = b2[k];
#pragma unroll
        for (int m = 0; m < CMID; m++) s += hid[b][m] * w2[m * 2 + k];
        float wv = 1.f / (1.f + expf(-s));
        wgt[b][k] = wv;
        outw[tid] = wv;
    }
    __syncthreads();
    if (tid < 8) {
        g_lohi[2 * tid + 0] = logf(wgt[tid][0] * 0.01f);
        g_lohi[2 * tid + 1] = logf(wgt[tid][1] * 0.60f);
    }
}

// ------------- kernel 4: fused fill + inner gather + 4x4 pool -----------
__global__ void __launch_bounds__(256) k_fused(const float* __restrict__ l,
                                               float* __restrict__ out) {
    if (blockIdx.x >= NB_INNER) {
        // constant fill (skips the inner region)
        int idx = (blockIdx.x - NB_INNER) * 256 + threadIdx.x;  // float4 index
        int plane = idx >> 11;
        int rem = idx & 2047;
        int h = rem >> 5, w4 = rem & 31;
        if (h < 16 && w4 < 8) return;
        float v = g_cval[plane];
        ((float4*)out)[idx] = make_float4(v, v, v, v);
        return;
    }

    __shared__ float st[8][68];
    int warpId = threadIdx.x >> 5;
    int lane   = threadIdx.x & 31;
    int wpos   = blockIdx.x * 8 + warpId;     // pooled position, w fastest
    int b   = wpos >> 9;
    int pos = wpos & 511;
    int h = pos >> 5, w = pos & 31;
    int tap = lane >> 3, c8 = lane & 7;

    float l0 = l[2*b], l1 = l[2*b + 1];
    float lo = g_lohi[2*b], hi = g_lohi[2*b + 1];
    float inv2 = 2.f / (hi - lo);

    // lane s (0..15) computes coordinate for sample s
    int s16 = lane & 15;
    int i = 4 * h + (s16 >> 2);
    int j = 4 * w + (s16 & 3);
    float2 pb = g_polar[(i << 7) | j];
    float gx = pb.y + l0;
    float gy = (pb.x - lo) * inv2 - 1.f + l1;
    float ix = fminf(fmaxf((gx + 1.f) * 112.f - 0.5f, 0.f), 223.f);
    float iy = fminf(fmaxf((gy + 1.f) * 112.f - 0.5f, 0.f), 223.f);

    const uint4* xt = (const uint4*)g_xTh;
    size_t bbase = (size_t)b * PLANE * 8;
    float acc[8];
#pragma unroll
    for (int k = 0; k < 8; k++) acc[k] = 0.f;

#pragma unroll
    for (int s = 0; s < 16; s++) {
        float ixs = __shfl_sync(0xffffffffu, ix, s);
        float iys = __shfl_sync(0xffffffffu, iy, s);
        float x0f = floorf(ixs), y0f = floorf(iys);
        float wx = ixs - x0f, wy = iys - y0f;
        int x0 = (int)x0f, y0 = (int)y0f;
        int x1 = min(x0 + 1, 223), y1 = min(y0 + 1, 223);
        int xs = (tap & 1) ? x1 : x0;
        int ys = (tap & 2) ? y1 : y0;
        float wt = ((tap & 1) ? wx : 1.f - wx) * ((tap & 2) ? wy : 1.f - wy);
        uint4 v = xt[bbase + (size_t)(ys * 224 + xs) * 8 + c8];
        half2* hp = (half2*)&v;
        float2 f0 = __half22float2(hp[0]);
        float2 f1 = __half22float2(hp[1]);
        float2 f2 = __half22float2(hp[2]);
        float2 f3 = __half22float2(hp[3]);
        acc[0] += wt * f0.x;  acc[1] += wt * f0.y;
        acc[2] += wt * f1.x;  acc[3] += wt * f1.y;
        acc[4] += wt * f2.x;  acc[5] += wt * f2.y;
        acc[6] += wt * f3.x;  acc[7] += wt * f3.y;
    }

    // sum the 4 taps (lane groups of 8)
#pragma unroll
    for (int k = 0; k < 8; k++) {
        acc[k] += __shfl_xor_sync(0xffffffffu, acc[k], 8);
        acc[k] += __shfl_xor_sync(0xffffffffu, acc[k], 16);
    }
    if (tap == 0) {
#pragma unroll
        for (int k = 0; k < 8; k++)
            st[warpId][8 * c8 + k] = acc[k] * (1.f / 16.f);
    }
    __syncthreads();

    // coalesced store: thread c gathers 8 consecutive w
    if (threadIdx.x < 64) {
        int c = threadIdx.x;
        int bpos = blockIdx.x * 8;
        int bB = bpos >> 9;
        int p0 = bpos & 511;
        int hB = p0 >> 5, w0 = p0 & 31;   // w0 multiple of 8
        float4 v0 = make_float4(st[0][c], st[1][c], st[2][c], st[3][c]);
        float4 v1 = make_float4(st[4][c], st[5][c], st[6][c], st[7][c]);
        size_t ob = (((size_t)(bB * CH + c) * PH + hB) * PW + w0);
        *(float4*)(out + ob)     = v0;
        *(float4*)(out + ob + 4) = v1;
    }
}

// ---------------------------------------------------------------------
extern "C" void kernel_launch(void* const* d_in, const int* in_sizes, int n_in,
                              void* d_out, int out_size) {
    const float* x  = (const float*)d_in[0];
    const float* l  = (const float*)d_in[1];
    const float* w1 = (const float*)d_in[2];
    const float* b1 = (const float*)d_in[3];
    const float* w2 = (const float*)d_in[4];
    const float* b2 = (const float*)d_in[5];
    float* out  = (float*)d_out;
    float* outw = out + POOLED_ELEMS;

    k_transpose<<<NTILES, 256>>>(x);
    k_mean_table<<<64, 256>>>();
    k_mlp<<<1, 256>>>(l, w1, b1, w2, b2, x, outw);
    k_fused<<<NB_INNER + NB_FILL, 256>>>(l, out);
}